// round 15
// baseline (speedup 1.0000x reference)
#include <cuda_runtime.h>
#include <float.h>

#define V    23
#define Hdim 256
#define Lseq 1024
#define TPB  128   // 4 warps, one chain (batch element) per CTA

// ---- Blackwell packed fp32x2 FMA (PTX-only; doubles fp32 throughput) ----
__device__ __forceinline__ unsigned long long ffma2(unsigned long long a,
                                                    unsigned long long b,
                                                    unsigned long long c) {
    unsigned long long d;
    asm("fma.rn.f32x2 %0, %1, %2, %3;" : "=l"(d) : "l"(a), "l"(b), "l"(c));
    return d;
}
__device__ __forceinline__ unsigned long long pack2(float x, float y) {
    unsigned long long d;
    asm("mov.b64 %0, {%1, %2};" : "=l"(d) : "f"(x), "f"(y));
    return d;
}
__device__ __forceinline__ float2 unpack2(unsigned long long a) {
    float2 r;
    asm("mov.b64 {%0, %1}, %2;" : "=f"(r.x), "=f"(r.y) : "l"(a));
    return r;
}

// Monotonic float->uint key, branchless: preserves float ordering
__device__ __forceinline__ unsigned fkey(float f) {
    unsigned u = __float_as_uint(f);
    return u ^ ((unsigned)(((int)u) >> 31) | 0x80000000u);
}

// Merge-reduce with selects (only the final mask-4/mask-2 rounds need them)
#define MRG(lo, hi, bit) do {                                   \
    float _keep = (lane & (bit)) ? (hi) : (lo);                 \
    float _send = (lane & (bit)) ? (lo) : (hi);                 \
    (lo) = _keep + __shfl_xor_sync(0xffffffffu, _send, (bit));  \
} while (0)

// mod-inverse table mod 23, 5 bits per entry, in two u64 constants
// s = 0..11 -> INV_LO, s = 12..22 -> INV_HI
#define INV_LO ( 0ull | (1ull<<5) | (12ull<<10) | (8ull<<15) | (6ull<<20) | \
                (14ull<<25) | (4ull<<30) | (10ull<<35) | (3ull<<40) |      \
                (18ull<<45) | (7ull<<50) | (21ull<<55) )
#define INV_HI ( 2ull | (16ull<<5) | (5ull<<10) | (20ull<<15) | (13ull<<20) | \
                (19ull<<25) | (9ull<<30) | (17ull<<35) | (15ull<<40) |       \
                (11ull<<45) | (22ull<<50) )

__global__ __launch_bounds__(TPB, 4)
void daf_kernel(const int* __restrict__ x_tokens,
                const float* __restrict__ W1,
                const float* __restrict__ b1,
                const float* __restrict__ W2,
                const float* __restrict__ b2,
                float* __restrict__ out)
{
    __shared__ __align__(16) float sW1[V * Hdim];  // 23552 B, row y contiguous
    __shared__ __align__(16) unsigned pm[2][8];    // [buf][0..3]=keys, [4..7]=idx
    __shared__ int stok[Lseq];                     // this chain's input tokens

    const int tid  = threadIdx.x;
    const int b    = blockIdx.x;
    const int lane = tid & 31;
    const int warp = tid >> 5;

    // Output-group repartition: each warp's 12 logits lie in ONE argmax group.
    // warp0: loc[0..11], warp1: loc[12..22], warp2: sc[0..11], warp3: sc[12..22]
    const int g    = warp >> 1;        // 0 = loc group, 1 = scale group
    const int base = (warp & 1) * 12;  // within-group offset (warps 1,3: 11 valid + 1 pad)

    // ---- one-time setup ----
    for (int i = tid; i < V * Hdim; i += TPB) sW1[i] = W1[i];
    {
        const int* tokrow = x_tokens + (size_t)b * Lseq;
        for (int i = tid; i < Lseq; i += TPB) stok[i] = tokrow[i];
    }

    // Per-lane h-row ownership: j_m = (m<4) ? 4*lane+m : 128 + 4*lane + (m-4)
    int jidx[8];
    #pragma unroll
    for (int m = 0; m < 8; ++m)
        jidx[m] = (m < 4) ? (4 * lane + m) : (124 + 4 * lane + m);

    // W2 in registers, PHASE-GROUPED select-free mapping:
    // scalar accumulator k (a_{k/2}, half k&1) holds within-warp output
    //   q(k) = (k>>2) + 3*((k&1)^b3) + 6*(((k>>1)&1)^b4)
    // so reduction rounds 16 and 8 pair WITHIN accumulator groups
    // {a0,a1} {a2,a3} {a4,a5}, letting each group's shuffles overlap the
    // next group's FMA issue. Register contents at the mask-4 boundary are
    // identical to the previous scheme (final rounds / q_loc unchanged).
    const int lb3 = (lane >> 3) & 1;
    const int lb4 = (lane >> 4) & 1;
    unsigned long long w2p[6][8];
    #pragma unroll
    for (int p = 0; p < 6; ++p) {
        int grp = p >> 1;
        int ad  = (p & 1) ^ lb4;
        int q0  = grp + 3 * lb3       + 6 * ad;   // scalar k=2p   (k&1=0)
        int q1  = grp + 3 * (1 ^ lb3) + 6 * ad;   // scalar k=2p+1 (k&1=1)
        int i0 = base + q0, i1 = base + q1;       // index within argmax group
        int o0 = g * V + i0, o1 = g * V + i1;     // W2 column
        #pragma unroll
        for (int m = 0; m < 8; ++m) {
            const float* row = W2 + jidx[m] * (2 * V);
            float v0 = (i0 < V) ? row[o0] : 0.0f;
            float v1 = (i1 < V) ? row[o1] : 0.0f;
            w2p[p][m] = pack2(v0, v1);
        }
    }

    // after the tree, u0 on this lane holds within-warp output q_loc:
    const int b1b = (lane >> 1) & 1, b2b = (lane >> 2) & 1;
    const int q_loc = b1b ? (2 + 3 * lb3 + 6 * lb4) : (b2b + 3 * lb3 + 6 * lb4);
    const int i_gr  = base + q_loc;               // index within argmax group
    const bool vld  = (i_gr < V);
    const float rbias = vld ? b2[g * V + i_gr] : 0.0f;

    // hpre replicated per warp, in registers. acc0 = 0 -> hpre = b1.
    float hp8[8];
    #pragma unroll
    for (int m = 0; m < 8; ++m) hp8[m] = b1[jidx[m]];

    float* op = out + (size_t)b * Lseq * V;

    __syncthreads();

    for (int t = 0; t < Lseq; ++t) {
        const int tok = stok[t];     // hoisted: LDS latency hidden under matvec

        float hv[8];
        #pragma unroll
        for (int m = 0; m < 8; ++m) hv[m] = fmaxf(hp8[m], 0.0f);

        // ---- group 0: a0,a1 then its private round-16/round-8 chain ----
        unsigned long long a0 = 0, a1 = 0;
        #pragma unroll
        for (int m = 0; m < 8; ++m) {
            unsigned long long hp = pack2(hv[m], hv[m]);
            a0 = ffma2(hp, w2p[0][m], a0);
            a1 = ffma2(hp, w2p[1][m], a1);
        }
        float2 qa0 = unpack2(a0), qa1 = unpack2(a1);
        float t00 = qa0.x + __shfl_xor_sync(0xffffffffu, qa1.x, 16);
        float t01 = qa0.y + __shfl_xor_sync(0xffffffffu, qa1.y, 16);

        // ---- group 1 (its FMAs overlap group 0's shuffles) ----
        unsigned long long a2 = 0, a3 = 0;
        #pragma unroll
        for (int m = 0; m < 8; ++m) {
            unsigned long long hp = pack2(hv[m], hv[m]);
            a2 = ffma2(hp, w2p[2][m], a2);
            a3 = ffma2(hp, w2p[3][m], a3);
        }
        float u0 = t00 + __shfl_xor_sync(0xffffffffu, t01, 8);
        float2 qa2 = unpack2(a2), qa3 = unpack2(a3);
        float t10 = qa2.x + __shfl_xor_sync(0xffffffffu, qa3.x, 16);
        float t11 = qa2.y + __shfl_xor_sync(0xffffffffu, qa3.y, 16);

        // ---- group 2 (overlaps group 1's shuffles) ----
        unsigned long long a4 = 0, a5 = 0;
        #pragma unroll
        for (int m = 0; m < 8; ++m) {
            unsigned long long hp = pack2(hv[m], hv[m]);
            a4 = ffma2(hp, w2p[4][m], a4);
            a5 = ffma2(hp, w2p[5][m], a5);
        }
        float u1 = t10 + __shfl_xor_sync(0xffffffffu, t11, 8);
        float2 qa4 = unpack2(a4), qa5 = unpack2(a5);
        float t20 = qa4.x + __shfl_xor_sync(0xffffffffu, qa5.x, 16);
        float t21 = qa4.y + __shfl_xor_sync(0xffffffffu, qa5.y, 16);
        float u2 = t20 + __shfl_xor_sync(0xffffffffu, t21, 8);

        // ---- final rounds (unchanged semantics) ----
        MRG(u0, u1, 4);
        u2 += __shfl_xor_sync(0xffffffffu, u2, 4);
        MRG(u0, u2, 2);
        u0 += __shfl_xor_sync(0xffffffffu, u0, 1);

        // ---- PRE-BAR argmax, EXACT (value redux-max, then index redux-min) ----
        unsigned key  = vld ? fkey(u0 + rbias) : 0u;
        unsigned km   = __reduce_max_sync(0xffffffffu, key);
        unsigned cand = (key == km && vld) ? (unsigned)i_gr : 1023u;
        unsigned imin = __reduce_min_sync(0xffffffffu, cand);
        if (lane == 0) { pm[t & 1][warp] = km; pm[t & 1][4 + warp] = imin; }
        __syncthreads();           // the ONLY barrier per step

        // ---- post-bar: combine 4 warp (key,idx) pairs -> loc, sc ----
        const uint4 pk = *reinterpret_cast<const uint4*>(&pm[t & 1][0]);
        const uint4 pi = *reinterpret_cast<const uint4*>(&pm[t & 1][4]);
        int loc = (pk.x >= pk.y) ? (int)pi.x : (int)pi.y;
        int sc  = (pk.z >= pk.w) ? (int)pi.z : (int)pi.w;

        // ---- token arithmetic, ALU-only ----
        int md = tok - loc;
        md += (md >> 31) & V;                       // (a0 - loc) mod 23
        unsigned inv = (unsigned)(((sc < 12) ? (INV_LO >> (5 * sc))
                                             : (INV_HI >> (5 * (sc - 12)))) & 31ull);
        int mprod = (int)inv * md;                  // <= 22*22 = 484
        int y = mprod - V * ((mprod * 5699) >> 17); // exact (inv*md) % 23

        // ---- one-hot output row (warp 3 only) ----
        if (warp == 3 && lane < V) op[lane] = (lane == y) ? 1.0f : 0.0f;
        op += V;

        // ---- per-warp state update: hpre += W1[y, :] ----
        const float4 wa = *reinterpret_cast<const float4*>(&sW1[y * Hdim + 4 * lane]);
        const float4 wb = *reinterpret_cast<const float4*>(&sW1[y * Hdim + 128 + 4 * lane]);
        hp8[0] += wa.x; hp8[1] += wa.y; hp8[2] += wa.z; hp8[3] += wa.w;
        hp8[4] += wb.x; hp8[5] += wb.y; hp8[6] += wb.z; hp8[7] += wb.w;
    }
}

extern "C" void kernel_launch(void* const* d_in, const int* in_sizes, int n_in,
                              void* d_out, int out_size) {
    const int*   x  = (const int*)d_in[0];
    const float* W1 = (const float*)d_in[1];
    const float* b1 = (const float*)d_in[2];
    const float* W2 = (const float*)d_in[3];
    const float* b2 = (const float*)d_in[4];
    int Bn = in_sizes[0] / Lseq;   // 512
    daf_kernel<<<Bn, TPB>>>(x, W1, b1, W2, b2, (float*)d_out);
}